// round 2
// baseline (speedup 1.0000x reference)
#include <cuda_runtime.h>
#include <cuda_fp16.h>
#include <cstdint>

#define TOKENS 8192
#define DIN    4096
#define DOUT   16384

// Scratch (device globals are the sanctioned scratch mechanism)
__device__ __half g_xn[(size_t)TOKENS * DIN];   // layernormed x, fp16 (64 MB)
__device__ __half g_ws[(size_t)DOUT * DIN];     // sign(W), fp16 (128 MB)

__device__ __forceinline__ uint32_t smem_u32(const void* p) {
    uint32_t a;
    asm("{ .reg .u64 t; cvta.to.shared.u64 t, %1; cvt.u32.u64 %0, t; }"
        : "=r"(a) : "l"(p));
    return a;
}

// ---------------------------------------------------------------------------
// Kernel 1: row layernorm (fp32 stats, ddof=1), write fp16 to g_xn
// ---------------------------------------------------------------------------
__global__ __launch_bounds__(256) void ln_kernel(const float* __restrict__ x) {
    int row = blockIdx.x;
    const float4* xr = (const float4*)(x + (size_t)row * DIN);
    float4 v[4];
    float s = 0.f, ss = 0.f;
#pragma unroll
    for (int i = 0; i < 4; i++) {
        v[i] = xr[threadIdx.x + i * 256];
        s  += v[i].x + v[i].y + v[i].z + v[i].w;
        ss += v[i].x * v[i].x + v[i].y * v[i].y + v[i].z * v[i].z + v[i].w * v[i].w;
    }
#pragma unroll
    for (int o = 16; o > 0; o >>= 1) {
        s  += __shfl_xor_sync(0xFFFFFFFFu, s, o);
        ss += __shfl_xor_sync(0xFFFFFFFFu, ss, o);
    }
    __shared__ float sh[2][8];
    __shared__ float sh_mean, sh_inv;
    int wid = threadIdx.x >> 5, lane = threadIdx.x & 31;
    if (lane == 0) { sh[0][wid] = s; sh[1][wid] = ss; }
    __syncthreads();
    if (threadIdx.x == 0) {
        float S = 0.f, SS = 0.f;
#pragma unroll
        for (int i = 0; i < 8; i++) { S += sh[0][i]; SS += sh[1][i]; }
        float mean = S * (1.f / DIN);
        float var  = fmaxf((SS - S * mean) * (1.f / (DIN - 1)), 0.f);
        sh_mean = mean;
        sh_inv  = 1.f / (sqrtf(var) + 1e-5f);
    }
    __syncthreads();
    float mean = sh_mean, inv = sh_inv;
    __half2* orow = (__half2*)(g_xn + (size_t)row * DIN);
#pragma unroll
    for (int i = 0; i < 4; i++) {
        int j = threadIdx.x + i * 256;
        orow[j * 2 + 0] = __floats2half2_rn((v[i].x - mean) * inv, (v[i].y - mean) * inv);
        orow[j * 2 + 1] = __floats2half2_rn((v[i].z - mean) * inv, (v[i].w - mean) * inv);
    }
}

// ---------------------------------------------------------------------------
// Kernel 2: binarize weights to fp16 {-1,0,+1}
// ---------------------------------------------------------------------------
__device__ __forceinline__ float sgnf(float a) {
    return (a > 0.f) ? 1.f : ((a < 0.f) ? -1.f : 0.f);
}

__global__ __launch_bounds__(256) void sign_kernel(const float4* __restrict__ w) {
    size_t i = (size_t)blockIdx.x * 256 + threadIdx.x;
    float4 v = w[i];
    __half2* o = (__half2*)g_ws;
    o[2 * i + 0] = __floats2half2_rn(sgnf(v.x), sgnf(v.y));
    o[2 * i + 1] = __floats2half2_rn(sgnf(v.z), sgnf(v.w));
}

// ---------------------------------------------------------------------------
// Kernel 3: HMMA (mma.sync m16n8k16) GEMM
//   CTA tile 128(M) x 128(N) x 64(K), 3-stage cp.async ring, 8 warps (2x4),
//   warp tile 64x32.  D[m][n] = sum_k xn[m][k]*ws[n][k]  (+bias)
// ---------------------------------------------------------------------------
constexpr int BM = 128, BN = 128, BK = 64;
constexpr int NK = DIN / BK;                 // 64 K-stages
constexpr int ASZ = BM * BK * 2;             // 16 KB
constexpr int BSZ = BN * BK * 2;             // 16 KB
constexpr int STG = ASZ + BSZ;               // 32 KB per stage
constexpr int NSTAGE = 3;
constexpr int SMEM_TOTAL = NSTAGE * STG;     // 96 KB

__device__ __forceinline__ void ldmx4(uint32_t* r, uint32_t addr) {
    asm volatile("ldmatrix.sync.aligned.m8n8.x4.shared.b16 {%0,%1,%2,%3}, [%4];"
                 : "=r"(r[0]), "=r"(r[1]), "=r"(r[2]), "=r"(r[3]) : "r"(addr));
}

__device__ __forceinline__ void mma16816(float* c, const uint32_t* a, const uint32_t* b) {
    asm volatile(
        "mma.sync.aligned.m16n8k16.row.col.f32.f16.f16.f32 "
        "{%0,%1,%2,%3}, {%4,%5,%6,%7}, {%8,%9}, {%0,%1,%2,%3};"
        : "+f"(c[0]), "+f"(c[1]), "+f"(c[2]), "+f"(c[3])
        : "r"(a[0]), "r"(a[1]), "r"(a[2]), "r"(a[3]), "r"(b[0]), "r"(b[1]));
}

// load one 32KB stage: A rows then B rows; 16B swizzled chunks (XOR-8)
__device__ __forceinline__ void load_stage(uint32_t sb, int buf, int kc,
                                           const __half* Ag, const __half* Bg, int tid) {
    uint32_t base = sb + buf * STG;
    int k0 = kc * BK;
#pragma unroll
    for (int i = 0; i < 4; i++) {               // A: 128 rows x 8 chunks
        int g = tid + i * 256;
        int row = g >> 3, c = g & 7;
        const void* src = Ag + (size_t)row * DIN + k0 + c * 8;
        uint32_t dst = base + row * 128 + ((c ^ (row & 7)) << 4);
        asm volatile("cp.async.cg.shared.global [%0], [%1], 16;" :: "r"(dst), "l"(src) : "memory");
    }
#pragma unroll
    for (int i = 0; i < 4; i++) {               // B: 128 rows x 8 chunks
        int g = tid + i * 256;
        int row = g >> 3, c = g & 7;
        const void* src = Bg + (size_t)row * DIN + k0 + c * 8;
        uint32_t dst = base + ASZ + row * 128 + ((c ^ (row & 7)) << 4);
        asm volatile("cp.async.cg.shared.global [%0], [%1], 16;" :: "r"(dst), "l"(src) : "memory");
    }
    asm volatile("cp.async.commit_group;" ::: "memory");
}

__global__ __launch_bounds__(256, 2)
void gemm_kernel(const float* __restrict__ bias, float* __restrict__ out) {
    extern __shared__ char smem[];
    uint32_t sb = smem_u32(smem);
    int tid = threadIdx.x, wid = tid >> 5, lane = tid & 31;
    int wm = wid & 1;        // 2 warps along M (64 rows each)
    int wn = wid >> 1;       // 4 warps along N (32 cols each)

    // tile map: bm fastest so a wave (296 CTAs) shares B column tiles in L2
    int bm = blockIdx.x & 63;
    int bn = blockIdx.x >> 6;
    int m0 = bm * BM, n0 = bn * BN;

    const __half* Ag = g_xn + (size_t)m0 * DIN;
    const __half* Bg = g_ws + (size_t)n0 * DIN;

    // ldmatrix lane address components
    int arow = wm * 64 + (lane & 15);           // + mt*16
    int ahalf = lane >> 4;                      // k-chunk offset 0/1
    int axm = arow & 7;
    int bg = lane >> 3, bj = lane & 7;
    int brow = wn * 32 + ((bg >> 1) << 3) + bj; // + npair*16
    int bhalf = bg & 1;
    int bxm = brow & 7;

    float acc[4][4][4];
#pragma unroll
    for (int i = 0; i < 4; i++)
#pragma unroll
        for (int j = 0; j < 4; j++)
#pragma unroll
            for (int t = 0; t < 4; t++) acc[i][j][t] = 0.f;

    load_stage(sb, 0, 0, Ag, Bg, tid);
    load_stage(sb, 1, 1, Ag, Bg, tid);

    for (int kc = 0; kc < NK; kc++) {
        if (kc == NK - 1) asm volatile("cp.async.wait_group 0;" ::: "memory");
        else              asm volatile("cp.async.wait_group 1;" ::: "memory");
        __syncthreads();

        int buf = kc % NSTAGE;
        if (kc + 2 < NK) load_stage(sb, (kc + 2) % NSTAGE, kc + 2, Ag, Bg, tid);

        uint32_t abase = sb + buf * STG;
        uint32_t bbase = abase + ASZ;
#pragma unroll
        for (int kk = 0; kk < 4; kk++) {
            uint32_t afr[4][4], bfr[2][4];
#pragma unroll
            for (int mt = 0; mt < 4; mt++) {
                int r = arow + mt * 16;
                int ch = kk * 2 + ahalf;
                ldmx4(afr[mt], abase + r * 128 + ((ch ^ axm) << 4));
            }
#pragma unroll
            for (int np = 0; np < 2; np++) {
                int r = brow + np * 16;
                int ch = kk * 2 + bhalf;
                ldmx4(bfr[np], bbase + r * 128 + ((ch ^ bxm) << 4));
            }
#pragma unroll
            for (int mt = 0; mt < 4; mt++)
#pragma unroll
                for (int nt = 0; nt < 4; nt++)
                    mma16816(acc[mt][nt], afr[mt], &bfr[nt >> 1][(nt & 1) * 2]);
        }
    }

    // epilogue: bias add + store
#pragma unroll
    for (int mt = 0; mt < 4; mt++) {
#pragma unroll
        for (int nt = 0; nt < 4; nt++) {
            int row = m0 + wm * 64 + mt * 16 + (lane >> 2);
            int col = n0 + wn * 32 + nt * 8 + 2 * (lane & 3);
            float2 bv = *(const float2*)(bias + col);
            float2 v0 = { acc[mt][nt][0] + bv.x, acc[mt][nt][1] + bv.y };
            float2 v1 = { acc[mt][nt][2] + bv.x, acc[mt][nt][3] + bv.y };
            *(float2*)(out + (size_t)row * DOUT + col)       = v0;
            *(float2*)(out + (size_t)(row + 8) * DOUT + col) = v1;
        }
    }
}

// ---------------------------------------------------------------------------
// kernel_launch
// ---------------------------------------------------------------------------
extern "C" void kernel_launch(void* const* d_in, const int* in_sizes, int n_in,
                              void* d_out, int out_size) {
    const float* x    = (const float*)d_in[0];
    const float* w    = (const float*)d_in[1];
    const float* bias = (const float*)d_in[2];
    float* out = (float*)d_out;

    cudaFuncSetAttribute(gemm_kernel, cudaFuncAttributeMaxDynamicSharedMemorySize, SMEM_TOTAL);

    ln_kernel<<<TOKENS, 256>>>(x);
    sign_kernel<<<(int)(((size_t)DOUT * DIN / 4) / 256), 256>>>((const float4*)w);

    int ntiles = (TOKENS / BM) * (DOUT / BN);   // 64 * 128 = 8192
    gemm_kernel<<<ntiles, 256, SMEM_TOTAL>>>(bias, out);
}